// round 6
// baseline (speedup 1.0000x reference)
#include <cuda_runtime.h>

#define H 512
#define W 1024
#define HW (H * W)
#define KTOP 200
#define KEYCAP 16384

// ---------------- device scratch (no allocations allowed) ----------------
__device__ float g_rmax[HW];
__device__ unsigned long long g_keys[KEYCAP];
__device__ int g_count;
__device__ int g_swap;   // 0: A==sem,B==hmp ; 1: A==hmp,B==sem
__device__ float g_cy[256];
__device__ float g_cx[256];

__device__ __forceinline__ float thr(float v) { return v > 0.1f ? v : -1.0f; }

// ---------------- kernel 0: decide which 524288-elem input is semantic ----
__global__ void k_probe(const unsigned* __restrict__ A) {
    __shared__ unsigned red[256];
    unsigned v = A[threadIdx.x];
    red[threadIdx.x] = v;
    __syncthreads();
    for (int s = 128; s > 0; s >>= 1) {
        if (threadIdx.x < s) red[threadIdx.x] = max(red[threadIdx.x], red[threadIdx.x + s]);
        __syncthreads();
    }
    if (threadIdx.x == 0) {
        g_swap = (red[0] < 19u) ? 0 : 1;  // small ints -> A is semantic_pred
        g_count = 0;
    }
}

// ---------------- kernel 1: horizontal 1x7 max of thresholded heatmap ----
__global__ void k_rowmax(const float* __restrict__ A, const float* __restrict__ B) {
    const float* __restrict__ hmp = g_swap ? A : B;
    int p = blockIdx.x * blockDim.x + threadIdx.x;
    if (p >= HW) return;
    int x = p & (W - 1);
    float m = -3.0f;
#pragma unroll
    for (int dx = -3; dx <= 3; dx++) {
        int xx = x + dx;
        if (xx >= 0 && xx < W) m = fmaxf(m, thr(hmp[p + dx]));
    }
    g_rmax[p] = m;
}

// ---------------- kernel 2: vertical 7x1 max + NMS + survivor compaction --
__global__ void k_nms(const float* __restrict__ A, const float* __restrict__ B) {
    const float* __restrict__ hmp = g_swap ? A : B;
    int p = blockIdx.x * blockDim.x + threadIdx.x;
    if (p >= HW) return;
    int y = p >> 10;
    float m = -3.0f;
#pragma unroll
    for (int dy = -3; dy <= 3; dy++) {
        int yy = y + dy;
        if (yy >= 0 && yy < H) m = fmaxf(m, g_rmax[p + dy * W]);
    }
    float v = thr(hmp[p]);
    // Only positive local maxima can ever be valid centers (score > 0).
    if (v > 0.0f && v == m) {
        int slot = atomicAdd(&g_count, 1);
        if (slot < KEYCAP) {
            // key: (score bits desc, then smaller index wins) -> larger key better
            g_keys[slot] = ((unsigned long long)__float_as_uint(v) << 32)
                         | (unsigned long long)(0xFFFFFFFFu - (unsigned)p);
        }
    }
}

// ---------------- kernel 3: exact top-200 select + sort by flat index -----
// Single block, 1024 threads, keys held in registers (16 per thread).
// Writes centers + valid as FLOAT (output buffer dtype is float32).
__global__ void __launch_bounds__(1024) k_topk(float* __restrict__ out_center,
                                               float* __restrict__ out_valid) {
    const int t = threadIdx.x;
    int n = g_count;
    if (n > KEYCAP) n = KEYCAP;

    unsigned long long kv[16];
#pragma unroll
    for (int j = 0; j < 16; j++) {
        int i = t + j * 1024;
        kv[j] = (i < n) ? g_keys[i] : 0ULL;
    }

    __shared__ int warpsum[32];
    __shared__ int totalSh;
    __shared__ unsigned long long s2[256];
    __shared__ int scnt;

    // Binary search for the exact 200th-largest key (keys are unique).
    unsigned long long lo = 0, hi = 0xFFFFFFFFFFFFFFFFULL;
    while (lo < hi) {
        unsigned long long mid = lo + ((hi - lo) >> 1) + 1ULL;
        int c = 0;
#pragma unroll
        for (int j = 0; j < 16; j++) c += (kv[j] >= mid) ? 1 : 0;
#pragma unroll
        for (int o = 16; o > 0; o >>= 1) c += __shfl_down_sync(0xffffffffu, c, o);
        if ((t & 31) == 0) warpsum[t >> 5] = c;
        __syncthreads();
        if (t < 32) {
            int c2 = warpsum[t];
#pragma unroll
            for (int o = 16; o > 0; o >>= 1) c2 += __shfl_down_sync(0xffffffffu, c2, o);
            if (t == 0) totalSh = c2;
        }
        __syncthreads();
        int total = totalSh;
        if (total >= KTOP) lo = mid; else hi = mid - 1ULL;
        __syncthreads();
    }
    unsigned long long P = lo;

    if (t == 0) scnt = 0;
    if (t < 256) s2[t] = 0xFFFFFFFFFFFFFFFFULL;
    __syncthreads();

    // Gather exactly the top-200; re-key as (idx asc, score bits) for ordering.
#pragma unroll
    for (int j = 0; j < 16; j++) {
        if (kv[j] != 0ULL && kv[j] >= P) {
            int pos = atomicAdd(&scnt, 1);
            if (pos < 256) {
                unsigned vb  = (unsigned)(kv[j] >> 32);
                unsigned idx = 0xFFFFFFFFu - (unsigned)(kv[j] & 0xFFFFFFFFULL);
                s2[pos] = ((unsigned long long)idx << 32) | (unsigned long long)vb;
            }
        }
    }
    __syncthreads();

    // Bitonic sort ascending over 256 (pads = ULLONG_MAX go to the end).
    for (int k = 2; k <= 256; k <<= 1) {
        for (int j = k >> 1; j > 0; j >>= 1) {
            if (t < 256) {
                int ixj = t ^ j;
                if (ixj > t) {
                    unsigned long long a = s2[t], b = s2[ixj];
                    bool asc = ((t & k) == 0);
                    if (asc ? (a > b) : (a < b)) { s2[t] = b; s2[ixj] = a; }
                }
            }
            __syncthreads();
        }
    }

    if (t < KTOP) {
        unsigned long long k2 = s2[t];
        unsigned idx = (unsigned)(k2 >> 32);
        float val = __uint_as_float((unsigned)(k2 & 0xFFFFFFFFULL));
        int cy = (int)(idx >> 10);
        int cx = (int)(idx & 1023u);
        out_center[2 * t]     = (float)cy;
        out_center[2 * t + 1] = (float)cx;
        int v = (val > 0.0f) ? 1 : 0;
        out_valid[t] = v ? 1.0f : 0.0f;
        g_cy[t] = v ? (float)cy : 1e10f;
        g_cx[t] = v ? (float)cx : 1e10f;
    }
}

// ---------------- kernel 4: nearest-center assignment (tile-pruned) -------
#define TS 32
__global__ void __launch_bounds__(256) k_assign(const int* __restrict__ A,
                                                const int* __restrict__ B,
                                                const float* __restrict__ off,
                                                float* __restrict__ out_inst) {
    const int* __restrict__ sem = g_swap ? B : A;

    __shared__ float red[256];
    __shared__ float rect[4];
    __shared__ float sdmin[256];
    __shared__ float scy[KTOP], scx[KTOP];
    __shared__ int sck[KTOP];
    __shared__ int sM;

    const int t = threadIdx.x;
    const int ty0 = blockIdx.y * TS;
    const int tx0 = blockIdx.x * TS;

    float ly[4], lx[4];
    float mnY = 1e30f, mxY = -1e30f, mnX = 1e30f, mxX = -1e30f;
#pragma unroll
    for (int i = 0; i < 4; i++) {
        int lp = t + i * 256;
        int py = ty0 + (lp >> 5);
        int px = tx0 + (lp & 31);
        int p  = py * W + px;
        ly[i] = __fadd_rn((float)py, off[p]);
        lx[i] = __fadd_rn((float)px, off[HW + p]);
        mnY = fminf(mnY, ly[i]); mxY = fmaxf(mxY, ly[i]);
        mnX = fminf(mnX, lx[i]); mxX = fmaxf(mxX, lx[i]);
    }

    // exact tile bounding rect of predicted locations
    red[t] = mnY; __syncthreads();
    for (int s = 128; s > 0; s >>= 1) { if (t < s) red[t] = fminf(red[t], red[t + s]); __syncthreads(); }
    if (t == 0) rect[0] = red[0];
    __syncthreads();
    red[t] = mxY; __syncthreads();
    for (int s = 128; s > 0; s >>= 1) { if (t < s) red[t] = fmaxf(red[t], red[t + s]); __syncthreads(); }
    if (t == 0) rect[1] = red[0];
    __syncthreads();
    red[t] = mnX; __syncthreads();
    for (int s = 128; s > 0; s >>= 1) { if (t < s) red[t] = fminf(red[t], red[t + s]); __syncthreads(); }
    if (t == 0) rect[2] = red[0];
    __syncthreads();
    red[t] = mxX; __syncthreads();
    for (int s = 128; s > 0; s >>= 1) { if (t < s) red[t] = fmaxf(red[t], red[t + s]); __syncthreads(); }
    if (t == 0) rect[3] = red[0];
    __syncthreads();

    const float ry0 = rect[0], ry1 = rect[1], rx0 = rect[2], rx1 = rect[3];

    // per-center min/max squared distance to the rect
    float dmx = 1e38f;
    if (t < KTOP) {
        float cy = g_cy[t], cx = g_cx[t];
        float a = fmaxf(fmaxf(ry0 - cy, cy - ry1), 0.0f);
        float b = fmaxf(fmaxf(rx0 - cx, cx - rx1), 0.0f);
        sdmin[t] = a * a + b * b;
        float c = fmaxf(cy - ry0, ry1 - cy);
        float d = fmaxf(cx - rx0, rx1 - cx);
        dmx = c * c + d * d;
    }
    red[t] = dmx; __syncthreads();
    for (int s = 128; s > 0; s >>= 1) { if (t < s) red[t] = fminf(red[t], red[t + s]); __syncthreads(); }

    if (t == 0) {
        float R = red[0];
        int m = 0;
        for (int k = 0; k < KTOP; k++) {
            if (sdmin[k] <= R) {   // <= keeps boundary ties => exact argmin semantics
                scy[m] = g_cy[k];
                scx[m] = g_cx[k];
                sck[m] = k;
                m++;
            }
        }
        sM = m;
    }
    __syncthreads();

    const int M = sM;
    float best[4] = {1e38f, 1e38f, 1e38f, 1e38f};
    int bk[4] = {0, 0, 0, 0};
    for (int c = 0; c < M; c++) {
        float cy = scy[c], cx = scx[c];
        int kk = sck[c];
#pragma unroll
        for (int i = 0; i < 4; i++) {
            // exact reference arithmetic: (cy-ly)^2 + (cx-lx)^2, no FMA contraction
            float dy = __fadd_rn(cy, -ly[i]);
            float dx = __fadd_rn(cx, -lx[i]);
            float d  = __fadd_rn(__fmul_rn(dy, dy), __fmul_rn(dx, dx));
            if (d < best[i]) { best[i] = d; bk[i] = kk; }  // first-wins ties (k asc)
        }
    }

#pragma unroll
    for (int i = 0; i < 4; i++) {
        int lp = t + i * 256;
        int py = ty0 + (lp >> 5);
        int px = tx0 + (lp & 31);
        int p  = py * W + px;
        int s  = sem[p];
        out_inst[p] = (s >= 11 && s <= 18) ? (float)(bk[i] + 1) : 0.0f;
    }
}

// ---------------- launch ---------------------------------------------------
extern "C" void kernel_launch(void* const* d_in, const int* in_sizes, int n_in,
                              void* d_out, int out_size) {
    // offsets is the unique 2*H*W-element input; the other two (in order) are A,B
    int offIdx = -1;
    for (int i = 0; i < n_in; i++) if (in_sizes[i] == 2 * HW) offIdx = i;
    const float* off = (const float*)d_in[offIdx];
    const void* AB[2];
    int m = 0;
    for (int i = 0; i < n_in; i++) if (i != offIdx) AB[m++] = d_in[i];
    const void* Aptr = AB[0];
    const void* Bptr = AB[1];

    float* out = (float*)d_out;  // [inst HW][center 400][valid 200], float32

    k_probe<<<1, 256>>>((const unsigned*)Aptr);
    k_rowmax<<<HW / 256, 256>>>((const float*)Aptr, (const float*)Bptr);
    k_nms<<<HW / 256, 256>>>((const float*)Aptr, (const float*)Bptr);
    k_topk<<<1, 1024>>>(out + HW, out + HW + 2 * KTOP);
    k_assign<<<dim3(W / TS, H / TS), 256>>>((const int*)Aptr, (const int*)Bptr, off, out);
}